// round 5
// baseline (speedup 1.0000x reference)
#include <cuda_runtime.h>
#include <math.h>

#define BB 2048
#define HH 256
#define TT 256
#define LN_EPS 1e-5f

// ---------------- persistent device scratch (no allocations) ----------------
__device__ float g_H0[2][BB * HH];
__device__ float g_C0[BB * HH];
__device__ float g_H1[2][BB * HH];
__device__ float g_C1[BB * HH];
__device__ float g_XP0[BB * 4 * HH];   // step-invariant layer0 input projection
__device__ float g_E1[BB * 128];
__device__ float g_ENC[BB * HH];

__device__ __forceinline__ float geluf(float v) {
    return 0.5f * v * (1.0f + erff(v * 0.7071067811865476f));
}
__device__ __forceinline__ float sigf(float v) {
    return 1.0f / (1.0f + expf(-v));
}

// ---------------- init: zero recurrent state ----------------
__global__ void k_init() {
    int stride = gridDim.x * blockDim.x;
    for (int i = blockIdx.x * blockDim.x + threadIdx.x; i < BB * HH; i += stride) {
        g_H0[0][i] = 0.f; g_H1[0][i] = 0.f; g_C0[i] = 0.f; g_C1[i] = 0.f;
    }
}

// ---------------- encoder stage 1: Linear(5->128)+GELU+LN ----------------
__global__ void k_enc1(const float* __restrict__ x,
                       const float* __restrict__ W1, const float* __restrict__ b1,
                       const float* __restrict__ g1, const float* __restrict__ be1) {
    int b = blockIdx.x, j = threadIdx.x;   // 128 threads
    __shared__ float xs[5];
    __shared__ float red[128];
    if (j < 5) xs[j] = x[b * 5 + j];
    __syncthreads();
    float s = b1[j];
#pragma unroll
    for (int k = 0; k < 5; k++) s = fmaf(xs[k], W1[j * 5 + k], s);
    float gv = geluf(s);
    red[j] = gv; __syncthreads();
#pragma unroll
    for (int o = 64; o > 0; o >>= 1) { if (j < o) red[j] += red[j + o]; __syncthreads(); }
    float m = red[0] * (1.0f / 128.0f);
    __syncthreads();
    float d = gv - m; red[j] = d * d; __syncthreads();
#pragma unroll
    for (int o = 64; o > 0; o >>= 1) { if (j < o) red[j] += red[j + o]; __syncthreads(); }
    float v = red[0] * (1.0f / 128.0f);
    g_E1[b * 128 + j] = d * rsqrtf(v + LN_EPS) * g1[j] + be1[j];
}

// ---------------- encoder stage 2: Linear(128->256)+GELU+LN ----------------
__global__ void k_enc2(const float* __restrict__ W2, const float* __restrict__ b2,
                       const float* __restrict__ g2, const float* __restrict__ be2) {
    int b = blockIdx.x, j = threadIdx.x;   // 256 threads
    __shared__ float hs[128];
    __shared__ float red[256];
    if (j < 128) hs[j] = g_E1[b * 128 + j];
    __syncthreads();
    float s = b2[j];
    const float* wr = W2 + j * 128;
#pragma unroll 8
    for (int k = 0; k < 128; k++) s = fmaf(hs[k], wr[k], s);
    float gv = geluf(s);
    red[j] = gv; __syncthreads();
#pragma unroll
    for (int o = 128; o > 0; o >>= 1) { if (j < o) red[j] += red[j + o]; __syncthreads(); }
    float m = red[0] * (1.0f / 256.0f);
    __syncthreads();
    float d = gv - m; red[j] = d * d; __syncthreads();
#pragma unroll
    for (int o = 128; o > 0; o >>= 1) { if (j < o) red[j] += red[j + o]; __syncthreads(); }
    float v = red[0] * (1.0f / 256.0f);
    g_ENC[b * HH + j] = d * rsqrtf(v + LN_EPS) * g2[j] + be2[j];
}

// ---------------- shared-tiled GEMM pass (accumulating) ----------------
// 256 threads. NU units/block, NRG = 256/NU row-groups of 8 rows -> BM = 8*NRG rows.
// Thread (u = tid%NU, rg = tid/NU) accumulates acc[q][r] for output cols
// (q*GS + u0 + u), rows (b0 + rg*8 + r).  A is [*,256] row-major, W rows len 256.
template <int NU>
__device__ __forceinline__ void gemm_pass(
    const float* __restrict__ A, const float* __restrict__ W,
    int b0, int u0, int GS, float acc[4][8], float* As, float* Ws) {
    constexpr int NRG = 256 / NU;
    constexpr int BM = NRG * 8;
    constexpr int SA = BM + 4;
    constexpr int SW = NU * 4 + 4;
    const int tid = threadIdx.x;
    const int u = tid % NU, rg = tid / NU;
    for (int kc = 0; kc < HH; kc += 32) {
        __syncthreads();
#pragma unroll
        for (int i = 0; i < BM / 32; i++) {           // A tile: BM x 32
            int v = tid + i * 256;
            int row = v >> 3, c4 = v & 7;
            float4 f = *(const float4*)(A + (b0 + row) * HH + kc + c4 * 4);
            As[(c4 * 4 + 0) * SA + row] = f.x;
            As[(c4 * 4 + 1) * SA + row] = f.y;
            As[(c4 * 4 + 2) * SA + row] = f.z;
            As[(c4 * 4 + 3) * SA + row] = f.w;
        }
#pragma unroll
        for (int i = 0; i < NU / 8; i++) {            // W tile: 4*NU x 32
            int v = tid + i * 256;
            int qu = v >> 3, c4 = v & 7;
            int q = qu & 3, uu = qu >> 2;
            float4 f = *(const float4*)(W + (q * GS + u0 + uu) * HH + kc + c4 * 4);
            Ws[(c4 * 4 + 0) * SW + uu * 4 + q] = f.x;
            Ws[(c4 * 4 + 1) * SW + uu * 4 + q] = f.y;
            Ws[(c4 * 4 + 2) * SW + uu * 4 + q] = f.z;
            Ws[(c4 * 4 + 3) * SW + uu * 4 + q] = f.w;
        }
        __syncthreads();
#pragma unroll
        for (int k = 0; k < 32; k++) {
            float4 a0 = *(const float4*)&As[k * SA + rg * 8];
            float4 a1 = *(const float4*)&As[k * SA + rg * 8 + 4];
            float4 wv = *(const float4*)&Ws[k * SW + u * 4];
            float av[8] = {a0.x, a0.y, a0.z, a0.w, a1.x, a1.y, a1.z, a1.w};
            float wq[4] = {wv.x, wv.y, wv.z, wv.w};
#pragma unroll
            for (int q = 0; q < 4; q++)
#pragma unroll
                for (int r = 0; r < 8; r++)
                    acc[q][r] = fmaf(wq[q], av[r], acc[q][r]);
        }
    }
}

// ---------------- xp0 = enc @ Wih0^T + bih0 + bhh0 (once) ----------------
__global__ void __launch_bounds__(256, 2) k_xp0(const float* __restrict__ Wih0,
                                                const float* __restrict__ bih0,
                                                const float* __restrict__ bhh0) {
    __shared__ __align__(16) float As[32 * 36];
    __shared__ __align__(16) float Ws[32 * 260];
    float acc[4][8];
#pragma unroll
    for (int q = 0; q < 4; q++)
#pragma unroll
        for (int r = 0; r < 8; r++) acc[q][r] = 0.f;
    int b0 = (blockIdx.x >> 2) * 32, u0 = (blockIdx.x & 3) * 64;
    gemm_pass<64>(g_ENC, Wih0, b0, u0, HH, acc, As, Ws);
    int u = threadIdx.x % 64, rg = threadIdx.x / 64;
    int ug = u0 + u;
#pragma unroll
    for (int q = 0; q < 4; q++) {
        float bs = bih0[q * HH + ug] + bhh0[q * HH + ug];
#pragma unroll
        for (int r = 0; r < 8; r++) {
            int b = b0 + rg * 8 + r;
            g_XP0[b * (4 * HH) + q * HH + ug] = acc[q][r] + bs;
        }
    }
}

// ---------------- kernel A: layer0 step t (blocks 0..255) + decoder step t-1 (32 blocks) ----
__global__ void __launch_bounds__(256, 2) kA(int t, int p, int nL0,
    const float* __restrict__ Whh0,
    const float* __restrict__ W3, const float* __restrict__ b3,
    const float* __restrict__ W4, const float* __restrict__ b4,
    float* __restrict__ out) {
    __shared__ __align__(16) float As[32 * 68];
    __shared__ __align__(16) float Ws[32 * 260];
    float acc[4][8];
#pragma unroll
    for (int q = 0; q < 4; q++)
#pragma unroll
        for (int r = 0; r < 8; r++) acc[q][r] = 0.f;
    int bid = blockIdx.x;
    if (bid < nL0) {
        // ---- layer0: gates = h0_prev @ Whh0^T + xp0 ----
        int b0 = (bid >> 2) * 32, u0 = (bid & 3) * 64;
        gemm_pass<64>(g_H0[p], Whh0, b0, u0, HH, acc, As, Ws);
        int u = threadIdx.x % 64, rg = threadIdx.x / 64;
        int ug = u0 + u;
        float* hout = g_H0[1 - p];
#pragma unroll
        for (int r = 0; r < 8; r++) {
            int b = b0 + rg * 8 + r;
            const float* xp = g_XP0 + b * (4 * HH);
            float gi = sigf(acc[0][r] + xp[0 * HH + ug]);
            float gf = sigf(acc[1][r] + xp[1 * HH + ug]);
            float gg = tanhf(acc[2][r] + xp[2 * HH + ug]);
            float go = sigf(acc[3][r] + xp[3 * HH + ug]);
            int ci = b * HH + ug;
            float c = gf * g_C0[ci] + gi * gg;
            g_C0[ci] = c;
            hout[ci] = go * tanhf(c);
        }
    } else {
        // ---- decoder for step t-1: d = gelu(h1 @ W3^T + b3); out = d @ W4^T + b4 ----
        int db = bid - nL0;
        int b0 = db * 64;
        gemm_pass<32>(g_H1[p], W3, b0, 0, 32, acc, As, Ws);
        int u = threadIdx.x % 32, rg = threadIdx.x / 32;   // u == lane id
        float p0[8], p1[8];
#pragma unroll
        for (int r = 0; r < 8; r++) { p0[r] = 0.f; p1[r] = 0.f; }
#pragma unroll
        for (int q = 0; q < 4; q++) {
            int col = q * 32 + u;
            float w40 = W4[col], w41 = W4[128 + col], bb = b3[col];
#pragma unroll
            for (int r = 0; r < 8; r++) {
                float d = geluf(acc[q][r] + bb);
                p0[r] = fmaf(d, w40, p0[r]);
                p1[r] = fmaf(d, w41, p1[r]);
            }
        }
#pragma unroll
        for (int o = 16; o > 0; o >>= 1) {
#pragma unroll
            for (int r = 0; r < 8; r++) {
                p0[r] += __shfl_xor_sync(0xffffffffu, p0[r], o);
                p1[r] += __shfl_xor_sync(0xffffffffu, p1[r], o);
            }
        }
        if (u == 0) {
            int ts = t - 1;
#pragma unroll
            for (int r = 0; r < 8; r++) {
                int b = b0 + rg * 8 + r;
                out[b * (TT * 2) + ts * 2 + 0] = p0[r] + b4[0];
                out[b * (TT * 2) + ts * 2 + 1] = p1[r] + b4[1];
            }
        }
    }
}

// ---------------- kernel B: layer1 step t ----------------
__global__ void __launch_bounds__(256, 2) kB(int p,
    const float* __restrict__ Wih1, const float* __restrict__ Whh1,
    const float* __restrict__ bih1, const float* __restrict__ bhh1) {
    __shared__ __align__(16) float As[32 * 36];
    __shared__ __align__(16) float Ws[32 * 260];
    float acc[4][8];
#pragma unroll
    for (int q = 0; q < 4; q++)
#pragma unroll
        for (int r = 0; r < 8; r++) acc[q][r] = 0.f;
    int b0 = (blockIdx.x >> 2) * 32, u0 = (blockIdx.x & 3) * 64;
    gemm_pass<64>(g_H0[1 - p], Wih1, b0, u0, HH, acc, As, Ws);  // input proj: h0(t)
    gemm_pass<64>(g_H1[p],     Whh1, b0, u0, HH, acc, As, Ws);  // recurrent: h1(t-1)
    int u = threadIdx.x % 64, rg = threadIdx.x / 64;
    int ug = u0 + u;
    float bs0 = bih1[0 * HH + ug] + bhh1[0 * HH + ug];
    float bs1 = bih1[1 * HH + ug] + bhh1[1 * HH + ug];
    float bs2 = bih1[2 * HH + ug] + bhh1[2 * HH + ug];
    float bs3 = bih1[3 * HH + ug] + bhh1[3 * HH + ug];
    float* hout = g_H1[1 - p];
#pragma unroll
    for (int r = 0; r < 8; r++) {
        int b = b0 + rg * 8 + r;
        float gi = sigf(acc[0][r] + bs0);
        float gf = sigf(acc[1][r] + bs1);
        float gg = tanhf(acc[2][r] + bs2);
        float go = sigf(acc[3][r] + bs3);
        int ci = b * HH + ug;
        float c = gf * g_C1[ci] + gi * gg;
        g_C1[ci] = c;
        hout[ci] = go * tanhf(c);
    }
}

extern "C" void kernel_launch(void* const* d_in, const int* in_sizes, int n_in,
                              void* d_out, int out_size) {
    const float* x    = (const float*)d_in[0];
    const float* W1   = (const float*)d_in[1];
    const float* b1   = (const float*)d_in[2];
    const float* g1   = (const float*)d_in[3];
    const float* be1  = (const float*)d_in[4];
    const float* W2   = (const float*)d_in[5];
    const float* b2   = (const float*)d_in[6];
    const float* g2   = (const float*)d_in[7];
    const float* be2  = (const float*)d_in[8];
    const float* Wih0 = (const float*)d_in[9];
    const float* Whh0 = (const float*)d_in[10];
    const float* bih0 = (const float*)d_in[11];
    const float* bhh0 = (const float*)d_in[12];
    const float* Wih1 = (const float*)d_in[13];
    const float* Whh1 = (const float*)d_in[14];
    const float* bih1 = (const float*)d_in[15];
    const float* bhh1 = (const float*)d_in[16];
    const float* W3   = (const float*)d_in[17];
    const float* b3   = (const float*)d_in[18];
    const float* W4   = (const float*)d_in[19];
    const float* b4   = (const float*)d_in[20];
    float* out = (float*)d_out;

    k_init<<<512, 256>>>();
    k_enc1<<<BB, 128>>>(x, W1, b1, g1, be1);
    k_enc2<<<BB, 256>>>(W2, b2, g2, be2);
    k_xp0<<<256, 256>>>(Wih0, bih0, bhh0);

    for (int t = 0; t <= TT; t++) {
        int p = t & 1;
        int nL0 = (t < TT) ? 256 : 0;
        int nDec = (t >= 1) ? 32 : 0;
        kA<<<nL0 + nDec, 256>>>(t, p, nL0, Whh0, W3, b3, W4, b4, out);
        if (t < TT)
            kB<<<256, 256>>>(p, Wih1, Whh1, bih1, bhh1);
    }
}

// round 8
// speedup vs baseline: 4.0034x; 4.0034x over previous
#include <cuda_runtime.h>
#include <cuda_bf16.h>
#include <math.h>
#include <stdint.h>

#define BB 2048
#define HH 256
#define TT 256
#define LN_EPS 1e-5f

typedef __nv_bfloat16 bf16;

// ---------------- persistent device scratch (no allocations) ----------------
__device__ float g_C0[BB * HH], g_C1[BB * HH];
__device__ __align__(16) bf16 g_H0h[2][BB * HH], g_H0l[2][BB * HH];
__device__ __align__(16) bf16 g_H1h[2][BB * HH], g_H1l[2][BB * HH];
__device__ float g_XP0[BB * 4 * HH];
__device__ float g_E1[BB * 128], g_ENC[BB * HH];
// weight images: gate-interleaved row-major [tile][n][K], bf16 hi/lo
__device__ __align__(16) bf16 g_I0h[8 * 128 * 256], g_I0l[8 * 128 * 256];   // Whh0
__device__ __align__(16) bf16 g_I1h[8 * 128 * 512], g_I1l[8 * 128 * 512];   // [Wih1 | Whh1]
__device__ __align__(16) bf16 g_I3h[128 * 256],     g_I3l[128 * 256];       // W3

__device__ __forceinline__ float geluf(float v) {
    return 0.5f * v * (1.0f + erff(v * 0.7071067811865476f));
}
__device__ __forceinline__ float sigf(float v) { return 1.0f / (1.0f + expf(-v)); }

__device__ __forceinline__ uint32_t smem_u32(const void* p) {
    uint32_t a;
    asm("{ .reg .u64 t; cvta.to.shared.u64 t, %1; cvt.u32.u64 %0, t; }" : "=r"(a) : "l"(p));
    return a;
}

#define LDSM4(R, addr) \
    asm volatile("ldmatrix.sync.aligned.m8n8.x4.shared.b16 {%0,%1,%2,%3}, [%4];" \
        : "=r"((R)[0]), "=r"((R)[1]), "=r"((R)[2]), "=r"((R)[3]) : "r"(addr))
#define MMA16816(C, A, B0R, B1R) \
    asm volatile("mma.sync.aligned.m16n8k16.row.col.f32.bf16.bf16.f32 " \
        "{%0,%1,%2,%3},{%4,%5,%6,%7},{%8,%9},{%0,%1,%2,%3};" \
        : "+f"((C)[0]), "+f"((C)[1]), "+f"((C)[2]), "+f"((C)[3]) \
        : "r"((A)[0]), "r"((A)[1]), "r"((A)[2]), "r"((A)[3]), "r"(B0R), "r"(B1R))

// ---------------- init ----------------
__global__ void k_init() {
    int stride = gridDim.x * blockDim.x;
    bf16 z = __float2bfloat16(0.f);
    for (int i = blockIdx.x * blockDim.x + threadIdx.x; i < BB * HH; i += stride) {
        g_C0[i] = 0.f; g_C1[i] = 0.f;
        g_H0h[0][i] = z; g_H0l[0][i] = z;
        g_H1h[1][i] = z; g_H1l[1][i] = z;
    }
}

// ---------------- weight image prep ----------------
__global__ void k_prep(const float* __restrict__ Whh0, const float* __restrict__ Wih1,
                       const float* __restrict__ Whh1, const float* __restrict__ W3) {
    int stride = gridDim.x * blockDim.x;
    const int N0 = 8 * 128 * 256;
    const int N1 = 8 * 128 * 512;
    const int N3 = 128 * 256;
    const int TOT = N0 + N1 + N3;
    for (int idx = blockIdx.x * blockDim.x + threadIdx.x; idx < TOT; idx += stride) {
        float v; bf16 *Dh, *Dl; int d;
        if (idx < N0) {
            int T = idx >> 15, r = idx & 32767;
            int n = r >> 8, k = r & 255;
            int row = (n & 3) * 256 + T * 32 + (n >> 2);
            v = Whh0[row * 256 + k]; Dh = g_I0h; Dl = g_I0l; d = idx;
        } else if (idx < N0 + N1) {
            int li = idx - N0;
            int T = li >> 16, r = li & 65535;
            int n = r >> 9, k = r & 511;
            int row = (n & 3) * 256 + T * 32 + (n >> 2);
            v = (k < 256) ? Wih1[row * 256 + k] : Whh1[row * 256 + (k - 256)];
            Dh = g_I1h; Dl = g_I1l; d = li;
        } else {
            int li = idx - N0 - N1;
            v = W3[li]; Dh = g_I3h; Dl = g_I3l; d = li;
        }
        bf16 hi = __float2bfloat16(v);
        bf16 lo = __float2bfloat16(v - __bfloat162float(hi));
        Dh[d] = hi; Dl[d] = lo;
    }
}

// ---------------- encoder ----------------
__global__ void k_enc1(const float* __restrict__ x,
                       const float* __restrict__ W1, const float* __restrict__ b1,
                       const float* __restrict__ g1, const float* __restrict__ be1) {
    int b = blockIdx.x, j = threadIdx.x;
    __shared__ float xs[5];
    __shared__ float red[128];
    if (j < 5) xs[j] = x[b * 5 + j];
    __syncthreads();
    float s = b1[j];
#pragma unroll
    for (int k = 0; k < 5; k++) s = fmaf(xs[k], W1[j * 5 + k], s);
    float gv = geluf(s);
    red[j] = gv; __syncthreads();
#pragma unroll
    for (int o = 64; o > 0; o >>= 1) { if (j < o) red[j] += red[j + o]; __syncthreads(); }
    float m = red[0] * (1.0f / 128.0f);
    __syncthreads();
    float d = gv - m; red[j] = d * d; __syncthreads();
#pragma unroll
    for (int o = 64; o > 0; o >>= 1) { if (j < o) red[j] += red[j + o]; __syncthreads(); }
    float v = red[0] * (1.0f / 128.0f);
    g_E1[b * 128 + j] = d * rsqrtf(v + LN_EPS) * g1[j] + be1[j];
}
__global__ void k_enc2(const float* __restrict__ W2, const float* __restrict__ b2,
                       const float* __restrict__ g2, const float* __restrict__ be2) {
    int b = blockIdx.x, j = threadIdx.x;
    __shared__ float hs[128];
    __shared__ float red[256];
    if (j < 128) hs[j] = g_E1[b * 128 + j];
    __syncthreads();
    float s = b2[j];
    const float* wr = W2 + j * 128;
#pragma unroll 8
    for (int k = 0; k < 128; k++) s = fmaf(hs[k], wr[k], s);
    float gv = geluf(s);
    red[j] = gv; __syncthreads();
#pragma unroll
    for (int o = 128; o > 0; o >>= 1) { if (j < o) red[j] += red[j + o]; __syncthreads(); }
    float m = red[0] * (1.0f / 256.0f);
    __syncthreads();
    float d = gv - m; red[j] = d * d; __syncthreads();
#pragma unroll
    for (int o = 128; o > 0; o >>= 1) { if (j < o) red[j] += red[j + o]; __syncthreads(); }
    float v = red[0] * (1.0f / 256.0f);
    g_ENC[b * HH + j] = d * rsqrtf(v + LN_EPS) * g2[j] + be2[j];
}

// ---------------- xp0 = enc @ Wih0^T + bih0 + bhh0 (SIMT, once) ----------------
__global__ void __launch_bounds__(256, 2) k_xp0(const float* __restrict__ Wih0,
                                                const float* __restrict__ bih0,
                                                const float* __restrict__ bhh0) {
    __shared__ __align__(16) float As[32 * 36];
    __shared__ __align__(16) float Ws[32 * 260];
    const int SA = 36, SW = 260;
    float acc[4][8];
#pragma unroll
    for (int q = 0; q < 4; q++)
#pragma unroll
        for (int r = 0; r < 8; r++) acc[q][r] = 0.f;
    int b0 = (blockIdx.x >> 2) * 32, u0 = (blockIdx.x & 3) * 64;
    const int tid = threadIdx.x;
    const int u = tid % 64, rg = tid / 64;
    for (int kc = 0; kc < HH; kc += 32) {
        __syncthreads();
        {
            int row = tid >> 3, c4 = tid & 7;
            float4 f = *(const float4*)(g_ENC + (b0 + row) * HH + kc + c4 * 4);
            As[(c4 * 4 + 0) * SA + row] = f.x; As[(c4 * 4 + 1) * SA + row] = f.y;
            As[(c4 * 4 + 2) * SA + row] = f.z; As[(c4 * 4 + 3) * SA + row] = f.w;
        }
#pragma unroll
        for (int i = 0; i < 8; i++) {
            int v = tid + i * 256;
            int qu = v >> 3, c4 = v & 7;
            int q = qu & 3, uu = qu >> 2;
            float4 f = *(const float4*)(Wih0 + (q * HH + u0 + uu) * HH + kc + c4 * 4);
            Ws[(c4 * 4 + 0) * SW + uu * 4 + q] = f.x; Ws[(c4 * 4 + 1) * SW + uu * 4 + q] = f.y;
            Ws[(c4 * 4 + 2) * SW + uu * 4 + q] = f.z; Ws[(c4 * 4 + 3) * SW + uu * 4 + q] = f.w;
        }
        __syncthreads();
#pragma unroll
        for (int k = 0; k < 32; k++) {
            float4 a0 = *(const float4*)&As[k * SA + rg * 8];
            float4 a1 = *(const float4*)&As[k * SA + rg * 8 + 4];
            float4 wv = *(const float4*)&Ws[k * SW + u * 4];
            float av[8] = {a0.x, a0.y, a0.z, a0.w, a1.x, a1.y, a1.z, a1.w};
            float wq[4] = {wv.x, wv.y, wv.z, wv.w};
#pragma unroll
            for (int q = 0; q < 4; q++)
#pragma unroll
                for (int r = 0; r < 8; r++)
                    acc[q][r] = fmaf(wq[q], av[r], acc[q][r]);
        }
    }
    int ug = u0 + u;
#pragma unroll
    for (int q = 0; q < 4; q++) {
        float bs = bih0[q * HH + ug] + bhh0[q * HH + ug];
#pragma unroll
        for (int r = 0; r < 8; r++) {
            int b = b0 + rg * 8 + r;
            g_XP0[b * (4 * HH) + q * HH + ug] = acc[q][r] + bs;
        }
    }
}

// ---------------- per-step kernel: layer0(t) | layer1(t-1) | decoder(t-2) ----------------
// CTA 128x128 tile, 8 warps (2M x 4N), warp tile 64x32.
// smem per K-chunk(32): A/B hi/lo tiles 128 rows x 32 k, padded row stride 40 bf16 (80B).
__global__ void __launch_bounds__(256, 2) k_step(int t,
    const float* __restrict__ bih1, const float* __restrict__ bhh1,
    const float* __restrict__ b3, const float* __restrict__ W4,
    const float* __restrict__ b4, float* __restrict__ out) {
    int bid = blockIdx.x;
    int role;
    if (bid < 128)      { if (t >= TT) return;          role = 0; }
    else if (bid < 256) { if (t < 1 || t > TT) return;  role = 1; }
    else                { if (t < 2) return;            role = 2; }
    const int p = t & 1;
    const int tid = threadIdx.x;
    const int lane = tid & 31, wid = tid >> 5;
    const int wm = wid & 1, wn = wid >> 1;
    const int m0 = wm * 64, n0 = wn * 32;

    __shared__ __align__(16) char SMEM[40960];
    bf16* sAh = (bf16*)SMEM;           // 5120 elems (128 x stride 40)
    bf16* sAl = sAh + 5120;
    bf16* sBh = sAl + 5120;
    bf16* sBl = sBh + 5120;
    float* sD = (float*)SMEM;          // epilogue dump: 128 x 68 floats = 34816B (overlay)

    // role-dependent sources
    const bf16 *A0h, *A0l, *A1h = 0, *A1l = 0, *Bh, *Bl;
    int bstride, nch, b0, T = 0;
    if (role == 0) {
        int mt = bid >> 3; T = bid & 7;
        b0 = mt * 128;
        A0h = g_H0h[p]; A0l = g_H0l[p];
        Bh = g_I0h + (size_t)T * 32768; Bl = g_I0l + (size_t)T * 32768;
        bstride = 256; nch = 8;
    } else if (role == 1) {
        int lb = bid - 128;
        int mt = lb >> 3; T = lb & 7;
        b0 = mt * 128;
        A0h = g_H0h[p]; A0l = g_H0l[p];
        A1h = g_H1h[p]; A1l = g_H1l[p];
        Bh = g_I1h + (size_t)T * 65536; Bl = g_I1l + (size_t)T * 65536;
        bstride = 512; nch = 16;
    } else {
        b0 = (bid - 256) * 128;
        A0h = g_H1h[p]; A0l = g_H1l[p];
        Bh = g_I3h; Bl = g_I3l;
        bstride = 256; nch = 8;
    }

    float C[4][4][4];
#pragma unroll
    for (int f = 0; f < 4; f++)
#pragma unroll
        for (int g = 0; g < 4; g++)
#pragma unroll
            for (int i = 0; i < 4; i++) C[f][g][i] = 0.f;

    // ldmatrix thread addresses (byte offsets in padded smem tiles)
    uint32_t aH = smem_u32(sAh) +
        (uint32_t)(((m0 + (lane & 7) + ((lane >> 3) & 1) * 8) * 40 + ((lane >> 4) & 1) * 8) * 2);
    uint32_t aL = aH + 10240u;
    uint32_t bH = smem_u32(sBh) +
        (uint32_t)(((n0 + ((lane >> 4) & 1) * 8 + (lane & 7)) * 40 + ((lane >> 3) & 1) * 8) * 2);
    uint32_t bL = bH + 10240u;

    for (int ch = 0; ch < nch; ch++) {
        const bf16 *gah, *gal;
        int kc, bk;
        if (role == 1 && ch >= 8) {
            gah = A1h; gal = A1l; kc = (ch - 8) * 32; bk = 256 + (ch - 8) * 32;
        } else {
            gah = A0h; gal = A0l; kc = ch * 32; bk = ch * 32;
        }
        __syncthreads();
#pragma unroll
        for (int i = 0; i < 2; i++) {
            int v = tid + i * 256;
            int row = v >> 2, q = v & 3;
            *((uint4*)(sAh + row * 40) + q) = *((const uint4*)(gah + (size_t)(b0 + row) * HH + kc) + q);
            *((uint4*)(sAl + row * 40) + q) = *((const uint4*)(gal + (size_t)(b0 + row) * HH + kc) + q);
            *((uint4*)(sBh + row * 40) + q) = *((const uint4*)(Bh + (size_t)row * bstride + bk) + q);
            *((uint4*)(sBl + row * 40) + q) = *((const uint4*)(Bl + (size_t)row * bstride + bk) + q);
        }
        __syncthreads();
#pragma unroll
        for (int ks = 0; ks < 2; ks++) {
            uint32_t Af[4][4], Alr[4][4], Bq[8];
#pragma unroll
            for (int f = 0; f < 4; f++) LDSM4(Af[f], aH + (uint32_t)(f * 1280 + ks * 32));
#pragma unroll
            for (int f = 0; f < 4; f++) LDSM4(Alr[f], aL + (uint32_t)(f * 1280 + ks * 32));
            LDSM4(&Bq[0], bH + (uint32_t)(ks * 32));
            LDSM4(&Bq[4], bH + (uint32_t)(1280 + ks * 32));
#pragma unroll
            for (int f = 0; f < 4; f++)
#pragma unroll
                for (int g = 0; g < 4; g++) MMA16816(C[f][g], Af[f], Bq[2 * g], Bq[2 * g + 1]);
#pragma unroll
            for (int f = 0; f < 4; f++)
#pragma unroll
                for (int g = 0; g < 4; g++) MMA16816(C[f][g], Alr[f], Bq[2 * g], Bq[2 * g + 1]);
            LDSM4(&Bq[0], bL + (uint32_t)(ks * 32));
            LDSM4(&Bq[4], bL + (uint32_t)(1280 + ks * 32));
#pragma unroll
            for (int f = 0; f < 4; f++)
#pragma unroll
                for (int g = 0; g < 4; g++) MMA16816(C[f][g], Af[f], Bq[2 * g], Bq[2 * g + 1]);
        }
    }

    // ---- epilogue: stage C through smem in two 64-col halves ----
    const int lane2 = lane & 3;
    float p0 = 0.f, p1 = 0.f;    // decoder accumulators (threads 0..127)
#pragma unroll
    for (int hh = 0; hh < 2; hh++) {
        __syncthreads();
        if ((wn >> 1) == hh) {
#pragma unroll
            for (int f = 0; f < 4; f++) {
                int r = m0 + f * 16 + (lane >> 2);
#pragma unroll
                for (int g = 0; g < 4; g++) {
                    int cl = (n0 & 63) + 8 * g + 2 * lane2;
                    sD[r * 68 + cl]           = C[f][g][0];
                    sD[r * 68 + cl + 1]       = C[f][g][1];
                    sD[(r + 8) * 68 + cl]     = C[f][g][2];
                    sD[(r + 8) * 68 + cl + 1] = C[f][g][3];
                }
            }
        }
        __syncthreads();
        if (role == 2) {
            if (tid < 128) {
#pragma unroll
                for (int c4 = 0; c4 < 16; c4++) {
                    float4 v4 = *(const float4*)&sD[tid * 68 + c4 * 4];
                    int col = hh * 64 + c4 * 4;
                    float d0 = geluf(v4.x + b3[col]);
                    float d1 = geluf(v4.y + b3[col + 1]);
                    float d2 = geluf(v4.z + b3[col + 2]);
                    float d3 = geluf(v4.w + b3[col + 3]);
                    p0 = fmaf(d0, W4[col], p0);       p1 = fmaf(d0, W4[128 + col], p1);
                    p0 = fmaf(d1, W4[col + 1], p0);   p1 = fmaf(d1, W4[129 + col], p1);
                    p0 = fmaf(d2, W4[col + 2], p0);   p1 = fmaf(d2, W4[130 + col], p1);
                    p0 = fmaf(d3, W4[col + 3], p0);   p1 = fmaf(d3, W4[131 + col], p1);
                }
            }
        } else {
            int ut = tid & 15, rg = tid >> 4;
            int u = T * 32 + hh * 16 + ut;
            float* Cst = (role == 0) ? g_C0 : g_C1;
            bf16* Hh = (role == 0) ? g_H0h[1 - p] : g_H1h[1 - p];
            bf16* Hl = (role == 0) ? g_H0l[1 - p] : g_H1l[1 - p];
            float bsi = 0.f, bsf = 0.f, bsg = 0.f, bso = 0.f;
            if (role == 1) {
                bsi = bih1[u] + bhh1[u];
                bsf = bih1[256 + u] + bhh1[256 + u];
                bsg = bih1[512 + u] + bhh1[512 + u];
                bso = bih1[768 + u] + bhh1[768 + u];
            }
#pragma unroll
            for (int r = 0; r < 8; r++) {
                int row = rg * 8 + r;
                int b = b0 + row;
                float4 gv = *(const float4*)&sD[row * 68 + ut * 4];
                float pi, pf, pg, po;
                if (role == 0) {
                    const float* xp = g_XP0 + (size_t)b * 1024;
                    pi = gv.x + xp[u]; pf = gv.y + xp[256 + u];
                    pg = gv.z + xp[512 + u]; po = gv.w + xp[768 + u];
                } else {
                    pi = gv.x + bsi; pf = gv.y + bsf; pg = gv.z + bsg; po = gv.w + bso;
                }
                float gi = sigf(pi), gf = sigf(pf), gg = tanhf(pg), go = sigf(po);
                int ci = b * HH + u;
                float c = gf * Cst[ci] + gi * gg;
                Cst[ci] = c;
                float h = go * tanhf(c);
                bf16 h16 = __float2bfloat16(h);
                Hh[ci] = h16;
                Hl[ci] = __float2bfloat16(h - __bfloat162float(h16));
            }
        }
    }
    if (role == 2 && tid < 128) {
        int ts = t - 2;
        int b = b0 + tid;
        out[b * (TT * 2) + ts * 2 + 0] = p0 + b4[0];
        out[b * (TT * 2) + ts * 2 + 1] = p1 + b4[1];
    }
}

extern "C" void kernel_launch(void* const* d_in, const int* in_sizes, int n_in,
                              void* d_out, int out_size) {
    const float* x    = (const float*)d_in[0];
    const float* W1   = (const float*)d_in[1];
    const float* b1   = (const float*)d_in[2];
    const float* g1   = (const float*)d_in[3];
    const float* be1  = (const float*)d_in[4];
    const float* W2   = (const float*)d_in[5];
    const float* b2   = (const float*)d_in[6];
    const float* g2   = (const float*)d_in[7];
    const float* be2  = (const float*)d_in[8];
    const float* Wih0 = (const float*)d_in[9];
    const float* Whh0 = (const float*)d_in[10];
    const float* bih0 = (const float*)d_in[11];
    const float* bhh0 = (const float*)d_in[12];
    const float* Wih1 = (const float*)d_in[13];
    const float* Whh1 = (const float*)d_in[14];
    const float* bih1 = (const float*)d_in[15];
    const float* bhh1 = (const float*)d_in[16];
    const float* W3   = (const float*)d_in[17];
    const float* b3   = (const float*)d_in[18];
    const float* W4   = (const float*)d_in[19];
    const float* b4   = (const float*)d_in[20];
    float* out = (float*)d_out;

    k_init<<<512, 256>>>();
    k_prep<<<832, 256>>>(Whh0, Wih1, Whh1, W3);
    k_enc1<<<BB, 128>>>(x, W1, b1, g1, be1);
    k_enc2<<<BB, 256>>>(W2, b2, g2, be2);
    k_xp0<<<256, 256>>>(Wih0, bih0, bhh0);

    for (int t = 0; t <= TT + 1; t++) {
        k_step<<<272, 256>>>(t, bih1, bhh1, b3, W4, b4, out);
    }
}

// round 9
// speedup vs baseline: 4.3675x; 1.0909x over previous
#include <cuda_runtime.h>
#include <cuda_bf16.h>
#include <math.h>
#include <stdint.h>

#define BB 2048
#define HH 256
#define TT 256
#define LN_EPS 1e-5f

typedef __nv_bfloat16 bf16;

// ---------------- persistent device scratch (no allocations) ----------------
__device__ float g_C0[BB * HH], g_C1[BB * HH];
__device__ __align__(16) bf16 g_H0h[2][BB * HH], g_H0l[2][BB * HH];
__device__ __align__(16) bf16 g_H1h[2][BB * HH], g_H1l[2][BB * HH];
__device__ float g_XP0[BB * 4 * HH];
__device__ float g_E1[BB * 128], g_ENC[BB * HH];
// weight images: gate-interleaved row-major [tile][n][K], bf16 hi/lo
__device__ __align__(16) bf16 g_I0h[8 * 128 * 256], g_I0l[8 * 128 * 256];   // Whh0
__device__ __align__(16) bf16 g_I1h[8 * 128 * 512], g_I1l[8 * 128 * 512];   // [Wih1 | Whh1]
__device__ __align__(16) bf16 g_I3h[128 * 256],     g_I3l[128 * 256];       // W3

__device__ __forceinline__ float geluf(float v) {
    return 0.5f * v * (1.0f + erff(v * 0.7071067811865476f));
}
__device__ __forceinline__ float sigf(float v) { return 1.0f / (1.0f + expf(-v)); }

__device__ __forceinline__ uint32_t smem_u32(const void* p) {
    uint32_t a;
    asm("{ .reg .u64 t; cvta.to.shared.u64 t, %1; cvt.u32.u64 %0, t; }" : "=r"(a) : "l"(p));
    return a;
}

#define LDSM4(R, addr) \
    asm volatile("ldmatrix.sync.aligned.m8n8.x4.shared.b16 {%0,%1,%2,%3}, [%4];" \
        : "=r"((R)[0]), "=r"((R)[1]), "=r"((R)[2]), "=r"((R)[3]) : "r"(addr))
#define MMA16816(C, A, B0R, B1R) \
    asm volatile("mma.sync.aligned.m16n8k16.row.col.f32.bf16.bf16.f32 " \
        "{%0,%1,%2,%3},{%4,%5,%6,%7},{%8,%9},{%0,%1,%2,%3};" \
        : "+f"((C)[0]), "+f"((C)[1]), "+f"((C)[2]), "+f"((C)[3]) \
        : "r"((A)[0]), "r"((A)[1]), "r"((A)[2]), "r"((A)[3]), "r"(B0R), "r"(B1R))
__device__ __forceinline__ void cpa16(uint32_t s, const void* g) {
    asm volatile("cp.async.cg.shared.global [%0], [%1], 16;" :: "r"(s), "l"(g));
}
#define CP_COMMIT() asm volatile("cp.async.commit_group;" ::: "memory")
#define CP_WAIT1()  asm volatile("cp.async.wait_group 1;" ::: "memory")
#define CP_WAIT0()  asm volatile("cp.async.wait_group 0;" ::: "memory")

// ---------------- init ----------------
__global__ void k_init() {
    int stride = gridDim.x * blockDim.x;
    bf16 z = __float2bfloat16(0.f);
    for (int i = blockIdx.x * blockDim.x + threadIdx.x; i < BB * HH; i += stride) {
        g_C0[i] = 0.f; g_C1[i] = 0.f;
        g_H0h[0][i] = z; g_H0l[0][i] = z;
        g_H1h[1][i] = z; g_H1l[1][i] = z;
    }
}

// ---------------- weight image prep ----------------
__global__ void k_prep(const float* __restrict__ Whh0, const float* __restrict__ Wih1,
                       const float* __restrict__ Whh1, const float* __restrict__ W3) {
    int stride = gridDim.x * blockDim.x;
    const int N0 = 8 * 128 * 256;
    const int N1 = 8 * 128 * 512;
    const int N3 = 128 * 256;
    const int TOT = N0 + N1 + N3;
    for (int idx = blockIdx.x * blockDim.x + threadIdx.x; idx < TOT; idx += stride) {
        float v; bf16 *Dh, *Dl; int d;
        if (idx < N0) {
            int T = idx >> 15, r = idx & 32767;
            int n = r >> 8, k = r & 255;
            int row = (n & 3) * 256 + T * 32 + (n >> 2);
            v = Whh0[row * 256 + k]; Dh = g_I0h; Dl = g_I0l; d = idx;
        } else if (idx < N0 + N1) {
            int li = idx - N0;
            int T = li >> 16, r = li & 65535;
            int n = r >> 9, k = r & 511;
            int row = (n & 3) * 256 + T * 32 + (n >> 2);
            v = (k < 256) ? Wih1[row * 256 + k] : Whh1[row * 256 + (k - 256)];
            Dh = g_I1h; Dl = g_I1l; d = li;
        } else {
            int li = idx - N0 - N1;
            v = W3[li]; Dh = g_I3h; Dl = g_I3l; d = li;
        }
        bf16 hi = __float2bfloat16(v);
        bf16 lo = __float2bfloat16(v - __bfloat162float(hi));
        Dh[d] = hi; Dl[d] = lo;
    }
}

// ---------------- encoder ----------------
__global__ void k_enc1(const float* __restrict__ x,
                       const float* __restrict__ W1, const float* __restrict__ b1,
                       const float* __restrict__ g1, const float* __restrict__ be1) {
    int b = blockIdx.x, j = threadIdx.x;
    __shared__ float xs[5];
    __shared__ float red[128];
    if (j < 5) xs[j] = x[b * 5 + j];
    __syncthreads();
    float s = b1[j];
#pragma unroll
    for (int k = 0; k < 5; k++) s = fmaf(xs[k], W1[j * 5 + k], s);
    float gv = geluf(s);
    red[j] = gv; __syncthreads();
#pragma unroll
    for (int o = 64; o > 0; o >>= 1) { if (j < o) red[j] += red[j + o]; __syncthreads(); }
    float m = red[0] * (1.0f / 128.0f);
    __syncthreads();
    float d = gv - m; red[j] = d * d; __syncthreads();
#pragma unroll
    for (int o = 64; o > 0; o >>= 1) { if (j < o) red[j] += red[j + o]; __syncthreads(); }
    float v = red[0] * (1.0f / 128.0f);
    g_E1[b * 128 + j] = d * rsqrtf(v + LN_EPS) * g1[j] + be1[j];
}

// coalesced smem-tiled: 256 blocks x 8 batches; W2 staged 64x128 per chunk
__global__ void __launch_bounds__(256) k_enc2(const float* __restrict__ W2,
                                              const float* __restrict__ b2,
                                              const float* __restrict__ g2,
                                              const float* __restrict__ be2) {
    __shared__ float xs[8][129];
    __shared__ float W2c[64][129];
    __shared__ float go_[8][260];
    int b0 = blockIdx.x * 8;
    int tid = threadIdx.x;
#pragma unroll
    for (int i = 0; i < 4; i++) {
        int v = tid + i * 256;
        int r = v >> 7, c = v & 127;
        xs[r][c] = g_E1[(b0 + r) * 128 + c];
    }
    int col = tid & 63;
    int bg = tid >> 6;           // 0..3 -> batches bg*2, bg*2+1
    for (int cc = 0; cc < 4; cc++) {
        __syncthreads();
#pragma unroll
        for (int i = 0; i < 32; i++) {
            int v = tid + i * 256;
            int r = v >> 7, c = v & 127;
            W2c[r][c] = W2[(cc * 64 + r) * 128 + c];
        }
        __syncthreads();
        int gcol = cc * 64 + col;
        float s0 = b2[gcol], s1 = s0;
        const float* x0 = xs[bg * 2];
        const float* x1 = xs[bg * 2 + 1];
#pragma unroll 8
        for (int k = 0; k < 128; k++) {
            float w = W2c[col][k];
            s0 = fmaf(x0[k], w, s0);
            s1 = fmaf(x1[k], w, s1);
        }
        go_[bg * 2][gcol] = geluf(s0);
        go_[bg * 2 + 1][gcol] = geluf(s1);
    }
    __syncthreads();
    // LN: one warp per batch
    int w = tid >> 5, lane = tid & 31;
    float v8[8], s = 0.f;
#pragma unroll
    for (int i = 0; i < 8; i++) { v8[i] = go_[w][lane + 32 * i]; s += v8[i]; }
#pragma unroll
    for (int o = 16; o > 0; o >>= 1) s += __shfl_xor_sync(0xffffffffu, s, o);
    float m = s * (1.0f / 256.0f);
    float vv = 0.f;
#pragma unroll
    for (int i = 0; i < 8; i++) { float d = v8[i] - m; vv += d * d; }
#pragma unroll
    for (int o = 16; o > 0; o >>= 1) vv += __shfl_xor_sync(0xffffffffu, vv, o);
    float rs = rsqrtf(vv * (1.0f / 256.0f) + LN_EPS);
#pragma unroll
    for (int i = 0; i < 8; i++) {
        int c = lane + 32 * i;
        g_ENC[(b0 + w) * HH + c] = (v8[i] - m) * rs * g2[c] + be2[c];
    }
}

// ---------------- xp0 = enc @ Wih0^T + bih0 + bhh0 (SIMT, once) ----------------
__global__ void __launch_bounds__(256, 2) k_xp0(const float* __restrict__ Wih0,
                                                const float* __restrict__ bih0,
                                                const float* __restrict__ bhh0) {
    __shared__ __align__(16) float As[32 * 36];
    __shared__ __align__(16) float Ws[32 * 260];
    const int SA = 36, SW = 260;
    float acc[4][8];
#pragma unroll
    for (int q = 0; q < 4; q++)
#pragma unroll
        for (int r = 0; r < 8; r++) acc[q][r] = 0.f;
    int b0 = (blockIdx.x >> 2) * 32, u0 = (blockIdx.x & 3) * 64;
    const int tid = threadIdx.x;
    const int u = tid % 64, rg = tid / 64;
    for (int kc = 0; kc < HH; kc += 32) {
        __syncthreads();
        {
            int row = tid >> 3, c4 = tid & 7;
            float4 f = *(const float4*)(g_ENC + (b0 + row) * HH + kc + c4 * 4);
            As[(c4 * 4 + 0) * SA + row] = f.x; As[(c4 * 4 + 1) * SA + row] = f.y;
            As[(c4 * 4 + 2) * SA + row] = f.z; As[(c4 * 4 + 3) * SA + row] = f.w;
        }
#pragma unroll
        for (int i = 0; i < 8; i++) {
            int v = tid + i * 256;
            int qu = v >> 3, c4 = v & 7;
            int q = qu & 3, uu = qu >> 2;
            float4 f = *(const float4*)(Wih0 + (q * HH + u0 + uu) * HH + kc + c4 * 4);
            Ws[(c4 * 4 + 0) * SW + uu * 4 + q] = f.x; Ws[(c4 * 4 + 1) * SW + uu * 4 + q] = f.y;
            Ws[(c4 * 4 + 2) * SW + uu * 4 + q] = f.z; Ws[(c4 * 4 + 3) * SW + uu * 4 + q] = f.w;
        }
        __syncthreads();
#pragma unroll
        for (int k = 0; k < 32; k++) {
            float4 a0 = *(const float4*)&As[k * SA + rg * 8];
            float4 a1 = *(const float4*)&As[k * SA + rg * 8 + 4];
            float4 wv = *(const float4*)&Ws[k * SW + u * 4];
            float av[8] = {a0.x, a0.y, a0.z, a0.w, a1.x, a1.y, a1.z, a1.w};
            float wq[4] = {wv.x, wv.y, wv.z, wv.w};
#pragma unroll
            for (int q = 0; q < 4; q++)
#pragma unroll
                for (int r = 0; r < 8; r++)
                    acc[q][r] = fmaf(wq[q], av[r], acc[q][r]);
        }
    }
    int ug = u0 + u;
#pragma unroll
    for (int q = 0; q < 4; q++) {
        float bs = bih0[q * HH + ug] + bhh0[q * HH + ug];
#pragma unroll
        for (int r = 0; r < 8; r++) {
            int b = b0 + rg * 8 + r;
            g_XP0[b * (4 * HH) + q * HH + ug] = acc[q][r] + bs;
        }
    }
}

// ---------------- per-step kernel: layer0(t) | layer1(t-1) | decoder(t-2) ----------------
// CTA 128x128 tile, 8 warps (2M x 4N). Double-buffered cp.async pipeline,
// smem buffer = 4 tiles (Ah, Al, Bh, Bl) of 128 x 32 bf16, padded stride 40.
#define BUFB 40960
__global__ void __launch_bounds__(256, 2) k_step(int t,
    const float* __restrict__ bih1, const float* __restrict__ bhh1,
    const float* __restrict__ b3, const float* __restrict__ W4,
    const float* __restrict__ b4, float* __restrict__ out) {
    int bid = blockIdx.x;
    int role;
    if (bid < 128)      { if (t >= TT) return;          role = 0; }
    else if (bid < 256) { if (t < 1 || t > TT) return;  role = 1; }
    else                { if (t < 2) return;            role = 2; }
    const int p = t & 1;
    const int tid = threadIdx.x;
    const int lane = tid & 31, wid = tid >> 5;
    const int wm = wid & 1, wn = wid >> 1;
    const int m0 = wm * 64, n0 = wn * 32;

    extern __shared__ __align__(16) char SMEM[];
    float* sD = (float*)SMEM;          // epilogue dump overlays buffer 0
    const uint32_t smem0 = smem_u32(SMEM);

    // role-dependent sources
    const bf16 *A0h, *A0l, *A1h = 0, *A1l = 0, *Bh, *Bl;
    int bstride, nch, b0, T = 0;
    if (role == 0) {
        int mt = bid >> 3; T = bid & 7;
        b0 = mt * 128;
        A0h = g_H0h[p]; A0l = g_H0l[p];
        Bh = g_I0h + (size_t)T * 32768; Bl = g_I0l + (size_t)T * 32768;
        bstride = 256; nch = 8;
    } else if (role == 1) {
        int lb = bid - 128;
        int mt = lb >> 3; T = lb & 7;
        b0 = mt * 128;
        A0h = g_H0h[p]; A0l = g_H0l[p];
        A1h = g_H1h[p]; A1l = g_H1l[p];
        Bh = g_I1h + (size_t)T * 65536; Bl = g_I1l + (size_t)T * 65536;
        bstride = 512; nch = 16;
    } else {
        b0 = (bid - 256) * 128;
        A0h = g_H1h[p]; A0l = g_H1l[p];
        Bh = g_I3h; Bl = g_I3l;
        bstride = 256; nch = 8;
    }

    float C[4][4][4];
#pragma unroll
    for (int f = 0; f < 4; f++)
#pragma unroll
        for (int g = 0; g < 4; g++)
#pragma unroll
            for (int i = 0; i < 4; i++) C[f][g][i] = 0.f;

    // cp.async issue for chunk ch into buffer ch&1 (8 x 16B per thread)
    const int ldrow = tid >> 2, ldq = tid & 3;       // rows: tid/4 and +64
    auto issue_load = [&](int ch) {
        const bf16 *gah, *gal; int kc, bk;
        if (role == 1 && ch >= 8) {
            gah = A1h; gal = A1l; kc = (ch - 8) * 32; bk = 256 + (ch - 8) * 32;
        } else {
            gah = A0h; gal = A0l; kc = ch * 32; bk = ch * 32;
        }
        uint32_t base = smem0 + (uint32_t)(ch & 1) * BUFB;
#pragma unroll
        for (int i = 0; i < 2; i++) {
            int row = ldrow + i * 64;
            uint32_t soff = (uint32_t)(row * 40 + ldq * 8) * 2u;
            cpa16(base + soff,          gah + (size_t)(b0 + row) * HH + kc + ldq * 8);
            cpa16(base + 10240u + soff, gal + (size_t)(b0 + row) * HH + kc + ldq * 8);
            cpa16(base + 20480u + soff, Bh + (size_t)row * bstride + bk + ldq * 8);
            cpa16(base + 30720u + soff, Bl + (size_t)row * bstride + bk + ldq * 8);
        }
        CP_COMMIT();
    };

    // ldmatrix thread addresses (byte offsets within a buffer)
    uint32_t aHo = (uint32_t)(((m0 + (lane & 7) + ((lane >> 3) & 1) * 8) * 40 +
                               ((lane >> 4) & 1) * 8) * 2);
    uint32_t bHo = 20480u + (uint32_t)(((n0 + ((lane >> 4) & 1) * 8 + (lane & 7)) * 40 +
                                        ((lane >> 3) & 1) * 8) * 2);

    issue_load(0);
    for (int ch = 0; ch < nch; ch++) {
        if (ch + 1 < nch) { issue_load(ch + 1); CP_WAIT1(); }
        else              { CP_WAIT0(); }
        __syncthreads();
        uint32_t base = smem0 + (uint32_t)(ch & 1) * BUFB;
        uint32_t aH = base + aHo, aL = aH + 10240u;
        uint32_t bH = base + bHo, bL = bH + 10240u;
#pragma unroll
        for (int ks = 0; ks < 2; ks++) {
            uint32_t Af[4][4], Alr[4][4], Bq[8];
#pragma unroll
            for (int f = 0; f < 4; f++) LDSM4(Af[f], aH + (uint32_t)(f * 1280 + ks * 32));
#pragma unroll
            for (int f = 0; f < 4; f++) LDSM4(Alr[f], aL + (uint32_t)(f * 1280 + ks * 32));
            LDSM4(&Bq[0], bH + (uint32_t)(ks * 32));
            LDSM4(&Bq[4], bH + (uint32_t)(1280 + ks * 32));
#pragma unroll
            for (int f = 0; f < 4; f++)
#pragma unroll
                for (int g = 0; g < 4; g++) MMA16816(C[f][g], Af[f], Bq[2 * g], Bq[2 * g + 1]);
#pragma unroll
            for (int f = 0; f < 4; f++)
#pragma unroll
                for (int g = 0; g < 4; g++) MMA16816(C[f][g], Alr[f], Bq[2 * g], Bq[2 * g + 1]);
            LDSM4(&Bq[0], bL + (uint32_t)(ks * 32));
            LDSM4(&Bq[4], bL + (uint32_t)(1280 + ks * 32));
#pragma unroll
            for (int f = 0; f < 4; f++)
#pragma unroll
                for (int g = 0; g < 4; g++) MMA16816(C[f][g], Af[f], Bq[2 * g], Bq[2 * g + 1]);
        }
        __syncthreads();
    }

    // ---- epilogue: stage C through smem in two 64-col halves ----
    const int lane2 = lane & 3;
    float p0 = 0.f, p1 = 0.f;    // decoder accumulators (threads 0..127)
#pragma unroll
    for (int hh = 0; hh < 2; hh++) {
        __syncthreads();
        if ((wn >> 1) == hh) {
#pragma unroll
            for (int f = 0; f < 4; f++) {
                int r = m0 + f * 16 + (lane >> 2);
#pragma unroll
                for (int g = 0; g < 4; g++) {
                    int cl = (n0 & 63) + 8 * g + 2 * lane2;
                    sD[r * 68 + cl]           = C[f][g][0];
                    sD[r * 68 + cl + 1]       = C[f][g][1];
                    sD[(r + 8) * 68 + cl]     = C[f][g][2];
                    sD[(r + 8) * 68 + cl + 1] = C[f][g][3];
                }
            }
        }
        __syncthreads();
        if (role == 2) {
            if (tid < 128) {
#pragma unroll
                for (int c4 = 0; c4 < 16; c4++) {
                    float4 v4 = *(const float4*)&sD[tid * 68 + c4 * 4];
                    int col = hh * 64 + c4 * 4;
                    float d0 = geluf(v4.x + b3[col]);
                    float d1 = geluf(v4.y + b3[col + 1]);
                    float d2 = geluf(v4.z + b3[col + 2]);
                    float d3 = geluf(v4.w + b3[col + 3]);
                    p0 = fmaf(d0, W4[col], p0);       p1 = fmaf(d0, W4[128 + col], p1);
                    p0 = fmaf(d1, W4[col + 1], p0);   p1 = fmaf(d1, W4[129 + col], p1);
                    p0 = fmaf(d2, W4[col + 2], p0);   p1 = fmaf(d2, W4[130 + col], p1);
                    p0 = fmaf(d3, W4[col + 3], p0);   p1 = fmaf(d3, W4[131 + col], p1);
                }
            }
        } else {
            int ut = tid & 15, rg = tid >> 4;
            int u = T * 32 + hh * 16 + ut;
            float* Cst = (role == 0) ? g_C0 : g_C1;
            bf16* Hh = (role == 0) ? g_H0h[1 - p] : g_H1h[1 - p];
            bf16* Hl = (role == 0) ? g_H0l[1 - p] : g_H1l[1 - p];
            float bsi = 0.f, bsf = 0.f, bsg = 0.f, bso = 0.f;
            if (role == 1) {
                bsi = bih1[u] + bhh1[u];
                bsf = bih1[256 + u] + bhh1[256 + u];
                bsg = bih1[512 + u] + bhh1[512 + u];
                bso = bih1[768 + u] + bhh1[768 + u];
            }
#pragma unroll
            for (int r = 0; r < 8; r++) {
                int row = rg * 8 + r;
                int b = b0 + row;
                float4 gv = *(const float4*)&sD[row * 68 + ut * 4];
                float pi, pf, pg, po;
                if (role == 0) {
                    const float* xp = g_XP0 + (size_t)b * 1024;
                    pi = gv.x + xp[u]; pf = gv.y + xp[256 + u];
                    pg = gv.z + xp[512 + u]; po = gv.w + xp[768 + u];
                } else {
                    pi = gv.x + bsi; pf = gv.y + bsf; pg = gv.z + bsg; po = gv.w + bso;
                }
                float gi = sigf(pi), gf = sigf(pf), gg = tanhf(pg), go = sigf(po);
                int ci = b * HH + u;
                float c = gf * Cst[ci] + gi * gg;
                Cst[ci] = c;
                float h = go * tanhf(c);
                bf16 h16 = __float2bfloat16(h);
                Hh[ci] = h16;
                Hl[ci] = __float2bfloat16(h - __bfloat162float(h16));
            }
        }
    }
    if (role == 2 && tid < 128) {
        int ts = t - 2;
        int b = b0 + tid;
        out[b * (TT * 2) + ts * 2 + 0] = p0 + b4[0];
        out[b * (TT * 2) + ts * 2 + 1] = p1 + b4[1];
    }
}

extern "C" void kernel_launch(void* const* d_in, const int* in_sizes, int n_in,
                              void* d_out, int out_size) {
    const float* x    = (const float*)d_in[0];
    const float* W1   = (const float*)d_in[1];
    const float* b1   = (const float*)d_in[2];
    const float* g1   = (const float*)d_in[3];
    const float* be1  = (const float*)d_in[4];
    const float* W2   = (const float*)d_in[5];
    const float* b2   = (const float*)d_in[6];
    const float* g2   = (const float*)d_in[7];
    const float* be2  = (const float*)d_in[8];
    const float* Wih0 = (const float*)d_in[9];
    const float* Whh0 = (const float*)d_in[10];
    const float* bih0 = (const float*)d_in[11];
    const float* bhh0 = (const float*)d_in[12];
    const float* Wih1 = (const float*)d_in[13];
    const float* Whh1 = (const float*)d_in[14];
    const float* bih1 = (const float*)d_in[15];
    const float* bhh1 = (const float*)d_in[16];
    const float* W3   = (const float*)d_in[17];
    const float* b3   = (const float*)d_in[18];
    const float* W4   = (const float*)d_in[19];
    const float* b4   = (const float*)d_in[20];
    float* out = (float*)d_out;

    static int smem_set = 0;
    if (!smem_set) {
        cudaFuncSetAttribute(k_step, cudaFuncAttributeMaxDynamicSharedMemorySize, 2 * BUFB);
        smem_set = 1;
    }

    k_init<<<512, 256>>>();
    k_prep<<<832, 256>>>(Whh0, Wih1, Whh1, W3);
    k_enc1<<<BB, 128>>>(x, W1, b1, g1, be1);
    k_enc2<<<256, 256>>>(W2, b2, g2, be2);
    k_xp0<<<256, 256>>>(Wih0, bih0, bhh0);

    for (int t = 0; t <= TT + 1; t++) {
        k_step<<<272, 256, 2 * BUFB>>>(t, bih1, bhh1, b3, W4, b4, out);
    }
}